// round 1
// baseline (speedup 1.0000x reference)
#include <cuda_runtime.h>
#include <math.h>

#define MROWS 16384
#define DIMX 1024
#define DPROJ 4192
#define DIN 2048
#define NH 32
#define HD 64
#define DS 32
#define LSEQ 4096
#define NC 64

// ---------------- scratch (static device globals; no allocation) ----------------
__device__ float g_h[(size_t)MROWS * DIMX];        //  64 MiB  LN output
__device__ float g_zx[(size_t)MROWS * DPROJ];      // 262 MiB  in-proj output
__device__ float g_Brot[(size_t)MROWS * DS];       //   2 MiB
__device__ float g_Crot[(size_t)MROWS * DS];       //   2 MiB
__device__ float g_states[(size_t)4 * NC * NH * HD * DS]; // 64 MiB
__device__ float g_stin[(size_t)4 * NC * NH * HD * DS];   // 64 MiB (S_in)
__device__ float g_csum[4 * NH * NC];
__device__ float g_y[(size_t)MROWS * DIN];         // 128 MiB

__device__ __forceinline__ float siluf(float x) { return x / (1.f + __expf(-x)); }

// ---------------- LayerNorm: x -> g_h ----------------
__global__ __launch_bounds__(256) void ln_kernel(const float* __restrict__ x,
                                                 const float* __restrict__ w,
                                                 const float* __restrict__ b)
{
    int row = blockIdx.x;
    int tid = threadIdx.x;
    const float* xr = x + (size_t)row * DIMX;
    float4 v = *(const float4*)(xr + tid * 4);
    float s  = v.x + v.y + v.z + v.w;
    float s2 = v.x*v.x + v.y*v.y + v.z*v.z + v.w*v.w;
    for (int o = 16; o; o >>= 1) {
        s  += __shfl_down_sync(0xffffffffu, s,  o);
        s2 += __shfl_down_sync(0xffffffffu, s2, o);
    }
    __shared__ float ss[8], ss2[8];
    if ((tid & 31) == 0) { ss[tid >> 5] = s; ss2[tid >> 5] = s2; }
    __syncthreads();
    if (tid == 0) {
        float t = 0.f, t2 = 0.f;
        for (int i = 0; i < 8; i++) { t += ss[i]; t2 += ss2[i]; }
        float mu = t / DIMX;
        ss[0]  = mu;
        ss2[0] = rsqrtf(t2 / DIMX - mu * mu + 1e-6f);
    }
    __syncthreads();
    float mu = ss[0], inv = ss2[0];
    int i0 = tid * 4;
    float4 wv = *(const float4*)(w + i0);
    float4 bv = *(const float4*)(b + i0);
    float4 o;
    o.x = (v.x - mu) * inv * wv.x + bv.x;
    o.y = (v.y - mu) * inv * wv.y + bv.y;
    o.z = (v.z - mu) * inv * wv.z + bv.z;
    o.w = (v.w - mu) * inv * wv.w + bv.w;
    *(float4*)(g_h + (size_t)row * DIMX + i0) = o;
}

// ---------------- fp32 GEMM: C[M,N] = A[M,K] @ B[K,N] (+ residual R) ----------------
// 128x128 block tile, K-tile 16, 256 threads, 8x8 per thread, double-buffered smem.
__global__ __launch_bounds__(256) void gemm_kernel(
    const float* __restrict__ A, const float* __restrict__ B,
    const float* __restrict__ R, float* __restrict__ C,
    int M, int N, int K)
{
    __shared__ float As[2][16][132];
    __shared__ float Bs[2][16][132];
    int tid  = threadIdx.x;
    int col0 = blockIdx.x * 128, row0 = blockIdx.y * 128;
    int tx = tid & 15, ty = tid >> 4;
    int ar = tid >> 2, ac = (tid & 3) * 4;
    int br = tid >> 5, bc = (tid & 31) * 4;
    bool bok = (col0 + bc) < N;

    const float* Ap  = A + (size_t)(row0 + ar) * K + ac;
    const float* Ap2 = Ap + (size_t)64 * K;
    const float* Bp  = B + (size_t)br * N + col0 + bc;
    const float* Bp2 = Bp + (size_t)8 * N;

    float acc[8][8];
#pragma unroll
    for (int i = 0; i < 8; i++)
#pragma unroll
        for (int j = 0; j < 8; j++) acc[i][j] = 0.f;

    const float4 za = make_float4(0.f, 0.f, 0.f, 0.f);
    // prologue: tile 0
    {
        float4 a0 = *(const float4*)Ap;
        float4 a1 = *(const float4*)Ap2;
        float4 b0 = bok ? *(const float4*)Bp  : za;
        float4 b1 = bok ? *(const float4*)Bp2 : za;
        As[0][ac+0][ar]    = a0.x; As[0][ac+1][ar]    = a0.y;
        As[0][ac+2][ar]    = a0.z; As[0][ac+3][ar]    = a0.w;
        As[0][ac+0][ar+64] = a1.x; As[0][ac+1][ar+64] = a1.y;
        As[0][ac+2][ar+64] = a1.z; As[0][ac+3][ar+64] = a1.w;
        *(float4*)&Bs[0][br][bc]   = b0;
        *(float4*)&Bs[0][br+8][bc] = b1;
    }
    __syncthreads();

    int KT = K >> 4;
    int buf = 0;
    for (int kt = 0; kt < KT; kt++) {
        float4 na0, na1, nb0, nb1;
        if (kt + 1 < KT) {
            na0 = *(const float4*)(Ap  + (kt + 1) * 16);
            na1 = *(const float4*)(Ap2 + (kt + 1) * 16);
            const float* pB  = Bp  + (size_t)(kt + 1) * 16 * N;
            const float* pB2 = Bp2 + (size_t)(kt + 1) * 16 * N;
            nb0 = bok ? *(const float4*)pB  : za;
            nb1 = bok ? *(const float4*)pB2 : za;
        }
#pragma unroll
        for (int kk = 0; kk < 16; kk++) {
            float a[8], bb[8];
            *(float4*)(a)      = *(const float4*)&As[buf][kk][ty * 8];
            *(float4*)(a + 4)  = *(const float4*)&As[buf][kk][ty * 8 + 4];
            *(float4*)(bb)     = *(const float4*)&Bs[buf][kk][tx * 8];
            *(float4*)(bb + 4) = *(const float4*)&Bs[buf][kk][tx * 8 + 4];
#pragma unroll
            for (int i = 0; i < 8; i++)
#pragma unroll
                for (int j = 0; j < 8; j++)
                    acc[i][j] = fmaf(a[i], bb[j], acc[i][j]);
        }
        if (kt + 1 < KT) {
            int nb = buf ^ 1;
            As[nb][ac+0][ar]    = na0.x; As[nb][ac+1][ar]    = na0.y;
            As[nb][ac+2][ar]    = na0.z; As[nb][ac+3][ar]    = na0.w;
            As[nb][ac+0][ar+64] = na1.x; As[nb][ac+1][ar+64] = na1.y;
            As[nb][ac+2][ar+64] = na1.z; As[nb][ac+3][ar+64] = na1.w;
            *(float4*)&Bs[nb][br][bc]   = nb0;
            *(float4*)&Bs[nb][br+8][bc] = nb1;
            __syncthreads();
            buf = nb;
        }
    }
#pragma unroll
    for (int i = 0; i < 8; i++) {
        int row = row0 + ty * 8 + i;
        const float* rr = R ? (R + (size_t)row * N) : (const float*)0;
        float* cr = C + (size_t)row * N;
#pragma unroll
        for (int j = 0; j < 8; j++) {
            int col = col0 + tx * 8 + j;
            if (col < N) {
                float v = acc[i][j];
                if (R) v += rr[col];
                cr[col] = v;
            }
        }
    }
}

// ---------------- silu + RoPE on B/C slices -> g_Brot, g_Crot ----------------
__global__ __launch_bounds__(256) void bcrope_kernel()
{
    int tid = threadIdx.x;
    int r8 = tid >> 5, n = tid & 31;
    int row = blockIdx.x * 8 + r8;
    int t = row & (LSEQ - 1);
    const float* base = g_zx + (size_t)row * DPROJ;
    float bo, co;
    if (n < 16) {
        int j = n >> 1;
        double invd = exp(-((double)j) * (log(10000.0) / 8.0));
        float inv = (float)invd;
        float ang = (float)t * inv;
        float sn, cs;
        sincosf(ang, &sn, &cs);
        float b1 = siluf(base[4096 + 2 * j]);
        float b2 = siluf(base[4096 + 2 * j + 1]);
        float c1 = siluf(base[4128 + 2 * j]);
        float c2 = siluf(base[4128 + 2 * j + 1]);
        if (n & 1) { bo = b1 * sn + b2 * cs; co = c1 * sn + c2 * cs; }
        else       { bo = b1 * cs - b2 * sn; co = c1 * cs - c2 * sn; }
    } else {
        bo = siluf(base[4096 + n]);
        co = siluf(base[4128 + n]);
    }
    g_Brot[(size_t)row * DS + n] = bo;
    g_Crot[(size_t)row * DS + n] = co;
}

// ---------------- SSD intra-chunk: Yd + D*xh -> g_y ; chunk states -> g_states ----------------
__global__ __launch_bounds__(256) void chunk_kernel(
    const float* __restrict__ dt_bias, const float* __restrict__ A_log,
    const float* __restrict__ Dv)
{
    int blk = blockIdx.x;
    int h = blk & 31; int bcid = blk >> 5; int c = bcid & 63; int b = bcid >> 6;
    __shared__ float Cs[64][33], Bsm[64][33], xh[64][65], Pt[64][17];
    __shared__ float acs[64], dtv[64], wv[64];
    int tid = threadIdx.x;
    int rowbase = b * LSEQ + c * 64;

    if (tid < 64) {
        float raw = g_zx[(size_t)(rowbase + tid) * DPROJ + 4160 + h] + dt_bias[h];
        dtv[tid] = (raw > 20.f) ? raw : log1pf(__expf(raw));
    }
    __syncthreads();
    if (tid == 0) {
        float A = -__expf(A_log[h]);
        float s = 0.f;
        for (int l = 0; l < 64; l++) { s += dtv[l] * A; acs[l] = s; }
    }
    for (int i = tid; i < 64 * 32; i += 256) {
        int l = i >> 5, n = i & 31;
        Bsm[l][n] = g_Brot[(size_t)(rowbase + l) * DS + n];
        Cs[l][n]  = g_Crot[(size_t)(rowbase + l) * DS + n];
    }
    for (int i = tid; i < 64 * 64; i += 256) {
        int l = i >> 6, p = i & 63;
        float v = g_zx[(size_t)(rowbase + l) * DPROJ + 2048 + h * 64 + p];
        xh[l][p] = siluf(v);
    }
    __syncthreads();

    int l  = tid >> 2;
    int pb = (tid & 3) << 4;
    float acc[16];
#pragma unroll
    for (int j = 0; j < 16; j++) acc[j] = 0.f;

    for (int st = 0; st < 4; st++) {
#pragma unroll
        for (int i = 0; i < 4; i++) {
            int ss = ((tid & 3) << 2) + i;
            int s  = (st << 4) + ss;
            float v = 0.f;
            if (s <= l) {
                float d = 0.f;
#pragma unroll
                for (int n = 0; n < 32; n++) d = fmaf(Cs[l][n], Bsm[s][n], d);
                v = d * __expf(acs[l] - acs[s]) * dtv[s];
            }
            Pt[l][ss] = v;
        }
        __syncthreads();
#pragma unroll
        for (int ss = 0; ss < 16; ss++) {
            float m = Pt[l][ss];
            int s = (st << 4) + ss;
#pragma unroll
            for (int j = 0; j < 16; j++) acc[j] = fmaf(m, xh[s][pb + j], acc[j]);
        }
        __syncthreads();
    }

    float Dh = Dv[h];
    float* yrow = g_y + (size_t)(rowbase + l) * DIN + h * HD + pb;
#pragma unroll
    for (int j = 0; j < 16; j++) yrow[j] = acc[j] + Dh * xh[l][pb + j];

    // states[p][n] = sum_l (dt*decay)[l] * xh[l][p] * B[l][n]
    if (tid < 64) wv[tid] = dtv[tid] * __expf(acs[63] - acs[tid]);
    __syncthreads();
    for (int i = tid; i < 64 * 32; i += 256) { int ll = i >> 5, n = i & 31; Bsm[ll][n] *= wv[ll]; }
    __syncthreads();
    int p  = tid >> 2;
    int nb = (tid & 3) << 3;
    float st8[8];
#pragma unroll
    for (int j = 0; j < 8; j++) st8[j] = 0.f;
    for (int l2 = 0; l2 < 64; l2++) {
        float xv = xh[l2][p];
#pragma unroll
        for (int j = 0; j < 8; j++) st8[j] = fmaf(xv, Bsm[l2][nb + j], st8[j]);
    }
    size_t sbase = ((size_t)((b * NC + c) * NH + h)) * (HD * DS);
#pragma unroll
    for (int j = 0; j < 8; j++) g_states[sbase + p * DS + nb + j] = st8[j];
    if (tid == 0) g_csum[(b * NH + h) * NC + c] = acs[63];
}

// ---------------- inter-chunk scan: S_in[c] = e^{s_{c-1}} S_in[c-1] + states[c-1] ----------------
__global__ __launch_bounds__(256) void scan_kernel()
{
    int bh = blockIdx.x;            // b*NH + h
    int b = bh >> 5, h = bh & 31;
    int tid = threadIdx.x;
    float S[8];
#pragma unroll
    for (int j = 0; j < 8; j++) S[j] = 0.f;
    for (int c = 0; c < NC; c++) {
        size_t base = ((size_t)((b * NC + c) * NH + h)) * (HD * DS);
#pragma unroll
        for (int j = 0; j < 8; j++) g_stin[base + tid + j * 256] = S[j];
        float e = __expf(g_csum[bh * NC + c]);
#pragma unroll
        for (int j = 0; j < 8; j++) S[j] = S[j] * e + g_states[base + tid + j * 256];
    }
}

// ---------------- Yo: y += exp(A_cs[l]) * (C_l . S_in) ----------------
__global__ __launch_bounds__(256) void yo_kernel(
    const float* __restrict__ dt_bias, const float* __restrict__ A_log)
{
    int blk = blockIdx.x;
    int h = blk & 31; int bcid = blk >> 5; int c = bcid & 63; int b = bcid >> 6;
    __shared__ float Cs[64][33], Sm[64][33];
    __shared__ float acs[64], dtv[64];
    int tid = threadIdx.x;
    int rowbase = b * LSEQ + c * 64;

    if (tid < 64) {
        float raw = g_zx[(size_t)(rowbase + tid) * DPROJ + 4160 + h] + dt_bias[h];
        dtv[tid] = (raw > 20.f) ? raw : log1pf(__expf(raw));
    }
    __syncthreads();
    if (tid == 0) {
        float A = -__expf(A_log[h]);
        float s = 0.f;
        for (int l = 0; l < 64; l++) { s += dtv[l] * A; acs[l] = s; }
    }
    size_t sbase = ((size_t)((b * NC + c) * NH + h)) * (HD * DS);
    for (int i = tid; i < 64 * 32; i += 256) {
        int l = i >> 5, n = i & 31;
        Cs[l][n] = g_Crot[(size_t)(rowbase + l) * DS + n];
        Sm[l][n] = g_stin[sbase + i];       // Sm[p][n]
    }
    __syncthreads();

    int l  = tid >> 2;
    int pb = (tid & 3) << 4;
    float el = __expf(acs[l]);
    float* yrow = g_y + (size_t)(rowbase + l) * DIN + h * HD;
#pragma unroll
    for (int j = 0; j < 16; j++) {
        int p = pb + j;
        float d = 0.f;
#pragma unroll
        for (int n = 0; n < 32; n++) d = fmaf(Cs[l][n], Sm[p][n], d);
        yrow[p] += el * d;
    }
}

// ---------------- gate (silu(z)) + RMSNorm, in place on g_y ----------------
__global__ __launch_bounds__(256) void gate_kernel(const float* __restrict__ rms_w)
{
    int row = blockIdx.x;
    int tid = threadIdx.x;
    float* yr = g_y + (size_t)row * DIN;
    const float* zr = g_zx + (size_t)row * DPROJ;
    float v[8]; float s2 = 0.f;
#pragma unroll
    for (int i = 0; i < 8; i++) {
        int idx = tid + i * 256;
        float y = yr[idx];
        float z = zr[idx];
        y *= siluf(z);
        v[i] = y;
        s2 = fmaf(y, y, s2);
    }
    for (int o = 16; o; o >>= 1) s2 += __shfl_down_sync(0xffffffffu, s2, o);
    __shared__ float red[8];
    if ((tid & 31) == 0) red[tid >> 5] = s2;
    __syncthreads();
    if (tid == 0) {
        float t = 0.f;
        for (int i = 0; i < 8; i++) t += red[i];
        red[0] = rsqrtf(t / DIN + 1e-6f);
    }
    __syncthreads();
    float sc = red[0];
#pragma unroll
    for (int i = 0; i < 8; i++) {
        int idx = tid + i * 256;
        yr[idx] = v[i] * sc * rms_w[idx];
    }
}

// ---------------- launch ----------------
extern "C" void kernel_launch(void* const* d_in, const int* in_sizes, int n_in,
                              void* d_out, int out_size)
{
    (void)in_sizes; (void)n_in; (void)out_size;
    const float* x       = (const float*)d_in[0];
    const float* ln_w    = (const float*)d_in[1];
    const float* ln_b    = (const float*)d_in[2];
    const float* W_in    = (const float*)d_in[3];
    const float* dt_bias = (const float*)d_in[4];
    const float* A_log   = (const float*)d_in[5];
    const float* Dv      = (const float*)d_in[6];
    const float* rms_w   = (const float*)d_in[7];
    const float* W_out   = (const float*)d_in[8];
    float* out = (float*)d_out;

    void *ph, *pzx, *py;
    cudaGetSymbolAddress(&ph,  g_h);
    cudaGetSymbolAddress(&pzx, g_zx);
    cudaGetSymbolAddress(&py,  g_y);

    ln_kernel<<<MROWS, 256>>>(x, ln_w, ln_b);
    gemm_kernel<<<dim3(33, 128), 256>>>((const float*)ph, W_in, (const float*)0,
                                        (float*)pzx, MROWS, DPROJ, DIMX);
    bcrope_kernel<<<MROWS / 8, 256>>>();
    chunk_kernel<<<4 * NC * NH, 256>>>(dt_bias, A_log, Dv);
    scan_kernel<<<4 * NH, 256>>>();
    yo_kernel<<<4 * NC * NH, 256>>>(dt_bias, A_log);
    gate_kernel<<<MROWS, 256>>>(rms_w);
    gemm_kernel<<<dim3(8, 128), 256>>>((const float*)py, W_out, x,
                                       out, MROWS, DIMX, DIN);
}

// round 4
// speedup vs baseline: 1.7024x; 1.7024x over previous
#include <cuda_runtime.h>
#include <cuda_bf16.h>
#include <math.h>
#include <stdint.h>

#define MROWS 16384
#define DIMX 1024
#define DPROJ 4192
#define DIN 2048
#define NH 32
#define HD 64
#define DS 32
#define LSEQ 4096
#define NC 64
#define NPAD_IN 4224

// ---------------- scratch ----------------
__device__ float g_zx[(size_t)MROWS * DPROJ];
__device__ float g_Brot[(size_t)MROWS * DS];
__device__ float g_Crot[(size_t)MROWS * DS];
__device__ float g_states[(size_t)4 * NC * NH * HD * DS];
__device__ float g_stin[(size_t)4 * NC * NH * HD * DS];
__device__ float g_csum[4 * NH * NC];
__device__ float g_y[(size_t)MROWS * DIN];
__device__ unsigned short g_Ahi[(size_t)MROWS * DIN];     // bf16 bits
__device__ unsigned short g_Alo[(size_t)MROWS * DIN];
__device__ unsigned short g_Bthi[(size_t)NPAD_IN * 1024]; // >= 1024*2048 too
__device__ unsigned short g_Btlo[(size_t)NPAD_IN * 1024];

__device__ __forceinline__ float siluf(float x) { return x / (1.f + __expf(-x)); }

__device__ __forceinline__ void splitbf(float f, unsigned short& hi, unsigned short& lo) {
    __nv_bfloat16 h = __float2bfloat16(f);
    float r = f - __bfloat162float(h);
    __nv_bfloat16 l = __float2bfloat16(r);
    hi = *reinterpret_cast<unsigned short*>(&h);
    lo = *reinterpret_cast<unsigned short*>(&l);
}

__device__ __forceinline__ uint32_t smem_u32(const void* p) {
    uint32_t a;
    asm("{ .reg .u64 t; cvta.to.shared.u64 t, %1; cvt.u32.u64 %0, t; }" : "=r"(a) : "l"(p));
    return a;
}
__device__ __forceinline__ void cpasync16(uint32_t dst, const void* src) {
    asm volatile("cp.async.cg.shared.global [%0], [%1], 16;" :: "r"(dst), "l"(src) : "memory");
}
__device__ __forceinline__ void mma16816(float* c, const uint32_t* a, const uint32_t* b) {
    asm volatile(
        "mma.sync.aligned.m16n8k16.row.col.f32.bf16.bf16.f32 "
        "{%0,%1,%2,%3}, {%4,%5,%6,%7}, {%8,%9}, {%0,%1,%2,%3};\n"
        : "+f"(c[0]), "+f"(c[1]), "+f"(c[2]), "+f"(c[3])
        : "r"(a[0]), "r"(a[1]), "r"(a[2]), "r"(a[3]), "r"(b[0]), "r"(b[1]));
}

// ---------------- LayerNorm: x -> (g_Ahi, g_Alo) bf16 hi/lo, K=1024 ----------------
__global__ __launch_bounds__(256) void ln_kernel(const float* __restrict__ x,
                                                 const float* __restrict__ w,
                                                 const float* __restrict__ b)
{
    int row = blockIdx.x;
    int tid = threadIdx.x;
    const float* xr = x + (size_t)row * DIMX;
    float4 v = *(const float4*)(xr + tid * 4);
    float s  = v.x + v.y + v.z + v.w;
    float s2 = v.x*v.x + v.y*v.y + v.z*v.z + v.w*v.w;
    for (int o = 16; o; o >>= 1) {
        s  += __shfl_down_sync(0xffffffffu, s,  o);
        s2 += __shfl_down_sync(0xffffffffu, s2, o);
    }
    __shared__ float ss[8], ss2[8];
    if ((tid & 31) == 0) { ss[tid >> 5] = s; ss2[tid >> 5] = s2; }
    __syncthreads();
    if (tid == 0) {
        float t = 0.f, t2 = 0.f;
        for (int i = 0; i < 8; i++) { t += ss[i]; t2 += ss2[i]; }
        float mu = t / DIMX;
        ss[0]  = mu;
        ss2[0] = rsqrtf(t2 / DIMX - mu * mu + 1e-6f);
    }
    __syncthreads();
    float mu = ss[0], inv = ss2[0];
    int i0 = tid * 4;
    float4 wv = *(const float4*)(w + i0);
    float4 bv = *(const float4*)(b + i0);
    float o0 = (v.x - mu) * inv * wv.x + bv.x;
    float o1 = (v.y - mu) * inv * wv.y + bv.y;
    float o2 = (v.z - mu) * inv * wv.z + bv.z;
    float o3 = (v.w - mu) * inv * wv.w + bv.w;
    ushort4 hv, lv;
    splitbf(o0, hv.x, lv.x); splitbf(o1, hv.y, lv.y);
    splitbf(o2, hv.z, lv.z); splitbf(o3, hv.w, lv.w);
    *(ushort4*)(g_Ahi + (size_t)row * DIMX + i0) = hv;
    *(ushort4*)(g_Alo + (size_t)row * DIMX + i0) = lv;
}

// ---------------- W[K,N] -> Bt[n][k] bf16 hi/lo (transpose + split) ----------------
__global__ __launch_bounds__(1024) void cvtT_kernel(const float* __restrict__ W, int K, int N)
{
    __shared__ float t[32][33];
    int k0 = blockIdx.x * 32, n0 = blockIdx.y * 32;
    int tx = threadIdx.x, ty = threadIdx.y;
    int n = n0 + tx;
    t[ty][tx] = (n < N) ? W[(size_t)(k0 + ty) * N + n] : 0.f;
    __syncthreads();
    float v = t[tx][ty];
    unsigned short hi, lo;
    splitbf(v, hi, lo);
    size_t o = (size_t)(n0 + ty) * K + k0 + tx;
    g_Bthi[o] = hi;
    g_Btlo[o] = lo;
}

// ---------------- mma.sync bf16 GEMM with hi/lo 3-pass split ----------------
// C[M,N] = A @ W (+R). A row-major [M,K], B as Bt[n][k] (K-major). 128x128x32 tile.
#define KSTAGE 40960
#define SMEM_GEMM (2 * KSTAGE)
__global__ __launch_bounds__(256, 1) void mma_gemm(
    const unsigned short* __restrict__ Ahi, const unsigned short* __restrict__ Alo,
    const unsigned short* __restrict__ Bhi, const unsigned short* __restrict__ Blo,
    const float* __restrict__ R, float* __restrict__ C, int N, int K)
{
    extern __shared__ char sm[];
    int tid = threadIdx.x, lane = tid & 31, wid = tid >> 5;
    int col0 = blockIdx.x * 128, row0 = blockIdx.y * 128;
    int g = lane >> 2, tig = lane & 3;
    int m0 = (wid >> 2) * 64, n0 = (wid & 3) * 32;
    uint32_t sb = smem_u32(sm);

    float acc[4][4][4];
#pragma unroll
    for (int i = 0; i < 4; i++)
#pragma unroll
        for (int j = 0; j < 4; j++)
#pragma unroll
            for (int q = 0; q < 4; q++) acc[i][j][q] = 0.f;

    const unsigned short* srcs[4] = {Ahi, Alo, Bhi, Blo};
    int rbs[4] = {row0, row0, col0, col0};

    int KT = K >> 5;
    // prologue: stage 0
    {
#pragma unroll
        for (int t = 0; t < 4; t++) {
#pragma unroll
            for (int cc = 0; cc < 2; cc++) {
                int chunk = tid + cc * 256;
                int row = chunk >> 2, c4 = chunk & 3;
                const void* src = srcs[t] + (size_t)(rbs[t] + row) * K + c4 * 8;
                cpasync16(sb + t * 10240 + row * 80 + c4 * 16, src);
            }
        }
        asm volatile("cp.async.commit_group;" ::: "memory");
    }

    for (int kt = 0; kt < KT; kt++) {
        if (kt + 1 < KT) {
            int buf = (kt + 1) & 1;
#pragma unroll
            for (int t = 0; t < 4; t++) {
#pragma unroll
                for (int cc = 0; cc < 2; cc++) {
                    int chunk = tid + cc * 256;
                    int row = chunk >> 2, c4 = chunk & 3;
                    const void* src = srcs[t] + (size_t)(rbs[t] + row) * K + (kt + 1) * 32 + c4 * 8;
                    cpasync16(sb + buf * KSTAGE + t * 10240 + row * 80 + c4 * 16, src);
                }
            }
            asm volatile("cp.async.commit_group;" ::: "memory");
            asm volatile("cp.async.wait_group 1;" ::: "memory");
        } else {
            asm volatile("cp.async.wait_group 0;" ::: "memory");
        }
        __syncthreads();

        const char* stb = sm + (kt & 1) * KSTAGE;
#pragma unroll
        for (int ks = 0; ks < 2; ks++) {
            int wb = (ks * 8 + tig) * 4;
            uint32_t bh[4][2], bl[4][2];
#pragma unroll
            for (int nt = 0; nt < 4; nt++) {
                const char* pb = stb + 20480 + (n0 + nt * 8 + g) * 80 + wb;
                bh[nt][0] = *(const uint32_t*)(pb);
                bh[nt][1] = *(const uint32_t*)(pb + 16);
                bl[nt][0] = *(const uint32_t*)(pb + 10240);
                bl[nt][1] = *(const uint32_t*)(pb + 10240 + 16);
            }
#pragma unroll
            for (int mt = 0; mt < 4; mt++) {
                const char* pa = stb + (m0 + mt * 16 + g) * 80 + wb;
                uint32_t ah[4], al[4];
                ah[0] = *(const uint32_t*)(pa);
                ah[1] = *(const uint32_t*)(pa + 8 * 80);
                ah[2] = *(const uint32_t*)(pa + 16);
                ah[3] = *(const uint32_t*)(pa + 8 * 80 + 16);
                al[0] = *(const uint32_t*)(pa + 10240);
                al[1] = *(const uint32_t*)(pa + 10240 + 8 * 80);
                al[2] = *(const uint32_t*)(pa + 10240 + 16);
                al[3] = *(const uint32_t*)(pa + 10240 + 8 * 80 + 16);
#pragma unroll
                for (int nt = 0; nt < 4; nt++) {
                    mma16816(acc[mt][nt], ah, bh[nt]);
                    mma16816(acc[mt][nt], ah, bl[nt]);
                    mma16816(acc[mt][nt], al, bh[nt]);
                }
            }
        }
        __syncthreads();
    }

    // epilogue
#pragma unroll
    for (int mt = 0; mt < 4; mt++) {
        int r0i = row0 + m0 + mt * 16 + g;
#pragma unroll
        for (int nt = 0; nt < 4; nt++) {
            int cc = col0 + n0 + nt * 8 + tig * 2;
            if (cc < N) {
                float* p0 = C + (size_t)r0i * N + cc;
                float* p1 = C + (size_t)(r0i + 8) * N + cc;
                float2 v0 = make_float2(acc[mt][nt][0], acc[mt][nt][1]);
                float2 v1 = make_float2(acc[mt][nt][2], acc[mt][nt][3]);
                if (R) {
                    const float* q0 = R + (size_t)r0i * N + cc;
                    const float* q1 = R + (size_t)(r0i + 8) * N + cc;
                    v0.x += q0[0]; v0.y += q0[1];
                    v1.x += q1[0]; v1.y += q1[1];
                }
                *(float2*)p0 = v0;
                *(float2*)p1 = v1;
            }
        }
    }
}

// ---------------- silu + RoPE on B/C slices -> g_Brot, g_Crot ----------------
__global__ __launch_bounds__(256) void bcrope_kernel()
{
    int tid = threadIdx.x;
    int r8 = tid >> 5, n = tid & 31;
    int row = blockIdx.x * 8 + r8;
    int t = row & (LSEQ - 1);
    const float* base = g_zx + (size_t)row * DPROJ;
    float bo, co;
    if (n < 16) {
        int j = n >> 1;
        double invd = exp(-((double)j) * (log(10000.0) / 8.0));
        float inv = (float)invd;
        float ang = (float)t * inv;
        float sn, cs;
        sincosf(ang, &sn, &cs);
        float b1 = siluf(base[4096 + 2 * j]);
        float b2 = siluf(base[4096 + 2 * j + 1]);
        float c1 = siluf(base[4128 + 2 * j]);
        float c2 = siluf(base[4128 + 2 * j + 1]);
        if (n & 1) { bo = b1 * sn + b2 * cs; co = c1 * sn + c2 * cs; }
        else       { bo = b1 * cs - b2 * sn; co = c1 * cs - c2 * sn; }
    } else {
        bo = siluf(base[4096 + n]);
        co = siluf(base[4128 + n]);
    }
    g_Brot[(size_t)row * DS + n] = bo;
    g_Crot[(size_t)row * DS + n] = co;
}

// ---------------- SSD intra-chunk ----------------
__global__ __launch_bounds__(256) void chunk_kernel(
    const float* __restrict__ dt_bias, const float* __restrict__ A_log,
    const float* __restrict__ Dv)
{
    int blk = blockIdx.x;
    int h = blk & 31; int bcid = blk >> 5; int c = bcid & 63; int b = bcid >> 6;
    __shared__ float Cs[64][33], Bsm[64][33], xh[64][65], Pt[64][17];
    __shared__ float acs[64], dtv[64], wv[64];
    int tid = threadIdx.x;
    int rowbase = b * LSEQ + c * 64;

    if (tid < 64) {
        float raw = g_zx[(size_t)(rowbase + tid) * DPROJ + 4160 + h] + dt_bias[h];
        dtv[tid] = (raw > 20.f) ? raw : log1pf(__expf(raw));
    }
    __syncthreads();
    if (tid == 0) {
        float A = -__expf(A_log[h]);
        float s = 0.f;
        for (int l = 0; l < 64; l++) { s += dtv[l] * A; acs[l] = s; }
    }
    for (int i = tid; i < 64 * 32; i += 256) {
        int l = i >> 5, n = i & 31;
        Bsm[l][n] = g_Brot[(size_t)(rowbase + l) * DS + n];
        Cs[l][n]  = g_Crot[(size_t)(rowbase + l) * DS + n];
    }
    for (int i = tid; i < 64 * 64; i += 256) {
        int l = i >> 6, p = i & 63;
        float v = g_zx[(size_t)(rowbase + l) * DPROJ + 2048 + h * 64 + p];
        xh[l][p] = siluf(v);
    }
    __syncthreads();

    int l  = tid >> 2;
    int pb = (tid & 3) << 4;
    float acc[16];
#pragma unroll
    for (int j = 0; j < 16; j++) acc[j] = 0.f;

    for (int st = 0; st < 4; st++) {
#pragma unroll
        for (int i = 0; i < 4; i++) {
            int ss = ((tid & 3) << 2) + i;
            int s  = (st << 4) + ss;
            float v = 0.f;
            if (s <= l) {
                float d = 0.f;
#pragma unroll
                for (int n = 0; n < 32; n++) d = fmaf(Cs[l][n], Bsm[s][n], d);
                v = d * __expf(acs[l] - acs[s]) * dtv[s];
            }
            Pt[l][ss] = v;
        }
        __syncthreads();
#pragma unroll
        for (int ss = 0; ss < 16; ss++) {
            float m = Pt[l][ss];
            int s = (st << 4) + ss;
#pragma unroll
            for (int j = 0; j < 16; j++) acc[j] = fmaf(m, xh[s][pb + j], acc[j]);
        }
        __syncthreads();
    }

    float Dh = Dv[h];
    float* yrow = g_y + (size_t)(rowbase + l) * DIN + h * HD + pb;
#pragma unroll
    for (int j = 0; j < 16; j++) yrow[j] = acc[j] + Dh * xh[l][pb + j];

    if (tid < 64) wv[tid] = dtv[tid] * __expf(acs[63] - acs[tid]);
    __syncthreads();
    for (int i = tid; i < 64 * 32; i += 256) { int ll = i >> 5, n = i & 31; Bsm[ll][n] *= wv[ll]; }
    __syncthreads();
    int p  = tid >> 2;
    int nb = (tid & 3) << 3;
    float st8[8];
#pragma unroll
    for (int j = 0; j < 8; j++) st8[j] = 0.f;
    for (int l2 = 0; l2 < 64; l2++) {
        float xv = xh[l2][p];
#pragma unroll
        for (int j = 0; j < 8; j++) st8[j] = fmaf(xv, Bsm[l2][nb + j], st8[j]);
    }
    size_t sbase = ((size_t)((b * NC + c) * NH + h)) * (HD * DS);
#pragma unroll
    for (int j = 0; j < 8; j++) g_states[sbase + p * DS + nb + j] = st8[j];
    if (tid == 0) g_csum[(b * NH + h) * NC + c] = acs[63];
}

// ---------------- inter-chunk scan ----------------
__global__ __launch_bounds__(256) void scan_kernel()
{
    int bh = blockIdx.x;
    int b = bh >> 5, h = bh & 31;
    int tid = threadIdx.x;
    float S[8];
#pragma unroll
    for (int j = 0; j < 8; j++) S[j] = 0.f;
    for (int c = 0; c < NC; c++) {
        size_t base = ((size_t)((b * NC + c) * NH + h)) * (HD * DS);
#pragma unroll
        for (int j = 0; j < 8; j++) g_stin[base + tid + j * 256] = S[j];
        float e = __expf(g_csum[bh * NC + c]);
#pragma unroll
        for (int j = 0; j < 8; j++) S[j] = S[j] * e + g_states[base + tid + j * 256];
    }
}

// ---------------- Yo ----------------
__global__ __launch_bounds__(256) void yo_kernel(
    const float* __restrict__ dt_bias, const float* __restrict__ A_log)
{
    int blk = blockIdx.x;
    int h = blk & 31; int bcid = blk >> 5; int c = bcid & 63; int b = bcid >> 6;
    __shared__ float Cs[64][33], Sm[64][33];
    __shared__ float acs[64], dtv[64];
    int tid = threadIdx.x;
    int rowbase = b * LSEQ + c * 64;

    if (tid < 64) {
        float raw = g_zx[(size_t)(rowbase + tid) * DPROJ + 4160 + h] + dt_bias[h];
        dtv[tid] = (raw > 20.f) ? raw : log1pf(__expf(raw));
    }
    __syncthreads();
    if (tid == 0) {
        float A = -__expf(A_log[h]);
        float s = 0.f;
        for (int l = 0; l < 64; l++) { s += dtv[l] * A; acs[l] = s; }
    }
    size_t sbase = ((size_t)((b * NC + c) * NH + h)) * (HD * DS);
    for (int i = tid; i < 64 * 32; i += 256) {
        int l = i >> 5, n = i & 31;
        Cs[l][n] = g_Crot[(size_t)(rowbase + l) * DS + n];
        Sm[l][n] = g_stin[sbase + i];
    }
    __syncthreads();

    int l  = tid >> 2;
    int pb = (tid & 3) << 4;
    float el = __expf(acs[l]);
    float* yrow = g_y + (size_t)(rowbase + l) * DIN + h * HD;
#pragma unroll
    for (int j = 0; j < 16; j++) {
        int p = pb + j;
        float d = 0.f;
#pragma unroll
        for (int n = 0; n < 32; n++) d = fmaf(Cs[l][n], Sm[p][n], d);
        yrow[p] += el * d;
    }
}

// ---------------- gate + RMSNorm -> (g_Ahi, g_Alo) bf16 hi/lo, K=2048 ----------------
__global__ __launch_bounds__(256) void gate_kernel(const float* __restrict__ rms_w)
{
    int row = blockIdx.x;
    int tid = threadIdx.x;
    const float* yr = g_y + (size_t)row * DIN;
    const float* zr = g_zx + (size_t)row * DPROJ;
    float v[8]; float s2 = 0.f;
#pragma unroll
    for (int i = 0; i < 8; i++) {
        int idx = tid + i * 256;
        float y = yr[idx];
        float z = zr[idx];
        y *= siluf(z);
        v[i] = y;
        s2 = fmaf(y, y, s2);
    }
    for (int o = 16; o; o >>= 1) s2 += __shfl_down_sync(0xffffffffu, s2, o);
    __shared__ float red[8];
    if ((tid & 31) == 0) red[tid >> 5] = s2;
    __syncthreads();
    if (tid == 0) {
        float t = 0.f;
        for (int i = 0; i < 8; i++) t += red[i];
        red[0] = rsqrtf(t / DIN + 1e-6f);
    }
    __syncthreads();
    float sc = red[0];
    size_t base = (size_t)row * DIN;
#pragma unroll
    for (int i = 0; i < 8; i++) {
        int idx = tid + i * 256;
        float f = v[i] * sc * rms_w[idx];
        unsigned short hi, lo;
        splitbf(f, hi, lo);
        g_Ahi[base + idx] = hi;
        g_Alo[base + idx] = lo;
    }
}

// ---------------- launch ----------------
extern "C" void kernel_launch(void* const* d_in, const int* in_sizes, int n_in,
                              void* d_out, int out_size)
{
    (void)in_sizes; (void)n_in; (void)out_size;
    const float* x       = (const float*)d_in[0];
    const float* ln_w    = (const float*)d_in[1];
    const float* ln_b    = (const float*)d_in[2];
    const float* W_in    = (const float*)d_in[3];
    const float* dt_bias = (const float*)d_in[4];
    const float* A_log   = (const float*)d_in[5];
    const float* Dv      = (const float*)d_in[6];
    const float* rms_w   = (const float*)d_in[7];
    const float* W_out   = (const float*)d_in[8];
    float* out = (float*)d_out;

    void *pzx, *pAhi, *pAlo, *pBhi, *pBlo;
    cudaGetSymbolAddress(&pzx,  g_zx);
    cudaGetSymbolAddress(&pAhi, g_Ahi);
    cudaGetSymbolAddress(&pAlo, g_Alo);
    cudaGetSymbolAddress(&pBhi, g_Bthi);
    cudaGetSymbolAddress(&pBlo, g_Btlo);

    static int attr_done = 0;
    if (!attr_done) {
        cudaFuncSetAttribute(mma_gemm, cudaFuncAttributeMaxDynamicSharedMemorySize, SMEM_GEMM);
        attr_done = 1;
    }

    ln_kernel<<<MROWS, 256>>>(x, ln_w, ln_b);
    cvtT_kernel<<<dim3(DIMX / 32, NPAD_IN / 32), dim3(32, 32)>>>(W_in, DIMX, DPROJ);
    mma_gemm<<<dim3(33, 128), 256, SMEM_GEMM>>>(
        (const unsigned short*)pAhi, (const unsigned short*)pAlo,
        (const unsigned short*)pBhi, (const unsigned short*)pBlo,
        (const float*)0, (float*)pzx, DPROJ, DIMX);
    bcrope_kernel<<<MROWS / 8, 256>>>();
    chunk_kernel<<<4 * NC * NH, 256>>>(dt_bias, A_log, Dv);
    scan_kernel<<<4 * NH, 256>>>();
    yo_kernel<<<4 * NC * NH, 256>>>(dt_bias, A_log);
    gate_kernel<<<MROWS, 256>>>(rms_w);
    cvtT_kernel<<<dim3(DIN / 32, DIMX / 32), dim3(32, 32)>>>(W_out, DIN, DIMX);
    mma_gemm<<<dim3(8, 128), 256, SMEM_GEMM>>>(
        (const unsigned short*)pAhi, (const unsigned short*)pAlo,
        (const unsigned short*)pBhi, (const unsigned short*)pBlo,
        x, out, DIMX, DIN);
}